// round 13
// baseline (speedup 1.0000x reference)
#include <cuda_runtime.h>
#include <cuda_fp16.h>
#include <cstdint>

#define BB   8
#define CC   64
#define HH   128
#define WW   128
#define OO   64
#define OOFF 18
#define KK   9
#define HWSZ (HH*WW)

#define PIX  128   // pixels per block in k_deform (one full row)
#define SSH  72    // s_samp pixel stride (halves) -> 144B rows, conflict-free ldmatrix
#define WSH  72    // s_w k-row stride (halves)
#define WBUFH (CC*WSH)    // 4608 halves per weight buffer
#define SBUFH (PIX*SSH)   // 9216 halves per sample buffer

#define NOFF 24    // offset-conv N padded to 24 (3 x n8 tiles)
#define XSTR 136   // offset-conv staged-row stride (halves)
#define WOSTR 72   // offset-conv weight k-stride (halves), layout [tap][n][k]

// ---------------- scratch (no allocations allowed) ----------------
__device__ __align__(16) __half g_xth[BB*HWSZ*CC];      // x in NHWC, fp16
__device__ __align__(16) float  g_off[BB*HWSZ*OOFF];    // offsets NHWC fp32
__device__ __align__(16) __half g_wth[KK*CC*OO];        // main weights [k][c][o] fp16
__device__ __align__(16) __half g_wtoffh[KK*NOFF*CC];   // offset weights [k][n][c] fp16, zero-pad

__device__ __forceinline__ uint32_t smem_u32(const void* p) {
    return (uint32_t)__cvta_generic_to_shared(p);
}

#define MMA_F16(d, a, b)                                                      \
    asm volatile("mma.sync.aligned.m16n8k16.row.col.f32.f16.f16.f32 "         \
                 "{%0,%1,%2,%3}, {%4,%5,%6,%7}, {%8,%9}, {%0,%1,%2,%3};"      \
                 : "+f"(d[0]), "+f"(d[1]), "+f"(d[2]), "+f"(d[3])             \
                 : "r"(a[0]), "r"(a[1]), "r"(a[2]), "r"(a[3]),                \
                   "r"(b[0]), "r"(b[1]))

#define LDSM_X4(r0, r1, r2, r3, addr)                                         \
    asm volatile("ldmatrix.sync.aligned.m8n8.x4.shared.b16 {%0,%1,%2,%3}, [%4];" \
                 : "=r"(r0), "=r"(r1), "=r"(r2), "=r"(r3) : "r"(addr))

#define LDSM_X4_T(r0, r1, r2, r3, addr)                                       \
    asm volatile("ldmatrix.sync.aligned.m8n8.x4.trans.shared.b16 {%0,%1,%2,%3}, [%4];" \
                 : "=r"(r0), "=r"(r1), "=r"(r2), "=r"(r3) : "r"(addr))

// ---------------- kernel 1: NCHW fp32 -> NHWC fp16 ----------------
__global__ void k_transpose(const float* __restrict__ x) {
    __shared__ float tile[64][33];
    int b   = blockIdx.z;
    int hw0 = blockIdx.x * 32;
    int c0  = blockIdx.y * 64;
    int tx = threadIdx.x, ty = threadIdx.y;
    const float* xp = x + (size_t)b * CC * HWSZ;
#pragma unroll
    for (int i = 0; i < 64; i += 8)
        tile[ty + i][tx] = xp[(size_t)(c0 + ty + i) * HWSZ + hw0 + tx];
    __syncthreads();
    __half2* op = (__half2*)(g_xth + (size_t)b * HWSZ * CC);
#pragma unroll
    for (int i = 0; i < 32; i += 8) {
        int row = ty + i;
        float lo = tile[2 * tx][row], hi = tile[2 * tx + 1][row];
        op[((size_t)(hw0 + row) * CC + c0) / 2 + tx] = __floats2half2_rn(lo, hi);
    }
}

// ---------------- kernel 2: weight prep ----------------
__global__ void k_wprep(const float* __restrict__ w, const float* __restrict__ woff) {
    int i = blockIdx.x * 256 + threadIdx.x;
    if (i < KK * CC * OO) {
        int k = i / (CC * OO);
        int r = i % (CC * OO);
        int c = r / OO;
        int o = r % OO;
        g_wth[i] = __float2half_rn(w[(o * CC + c) * KK + k]);
    }
    if (i < KK * NOFF * CC) {
        int t = i / (NOFF * CC);
        int r = i % (NOFF * CC);
        int n = r / CC;
        int c = r % CC;
        g_wtoffh[i] = (n < OOFF)
            ? __float2half_rn(woff[(n * CC + c) * KK + t])
            : __float2half_rn(0.f);
    }
}

// ---------------- kernel 3: offset conv via fp16 MMA ----------------
// Block = one output row. Stage 3 input rows (fp16, raw copy, zero-pad cols);
// 9 taps = shifted-A GEMMs, K=64 (4 k16 chunks), N=24 (18 used).
__global__ __launch_bounds__(256) void k_offconv(const float* __restrict__ boff) {
    extern __shared__ __align__(16) char smo[];
    __half* s_wo  = (__half*)smo;                        // [9][24][WOSTR] 31104 B
    __half* s_xr  = (__half*)(smo + 31104);              // [130][XSTR]    35360 B
    float*  s_off = (float*)(smo + 31104 + 35360);       // [128*18]        9216 B

    int tid  = threadIdx.x;
    int b    = blockIdx.y;
    int ho   = blockIdx.x;
    int lane = tid & 31;
    int wid  = tid >> 5;
    int g  = lane >> 2;
    int tg = lane & 3;
    int p0 = wid * 16;

    // stage all 9 taps' weights [t][n][k] with stride WOSTR
    {
        const uint4* src = (const uint4*)g_wtoffh;
        for (int i = tid; i < KK * NOFF * CC / 8; i += 256) {
            int tn = i >> 3, c8 = (i & 7) * 8;           // tn = t*24 + n
            *(uint4*)&s_wo[tn * WOSTR + c8] = src[i];
        }
    }

    float acc[3][4];
#pragma unroll
    for (int nt = 0; nt < 3; nt++)
#pragma unroll
        for (int c = 0; c < 4; c++) acc[nt][c] = 0.f;

#pragma unroll 1
    for (int ki = 0; ki < 3; ki++) {
        __syncthreads();
        int y = ho - 1 + ki;
        if (y >= 0 && y < HH) {
            const uint4* src = (const uint4*)(g_xth + (size_t)(b * HWSZ + y * WW) * CC);
#pragma unroll
            for (int t = 0; t < 4; t++) {
                int idx = tid + t * 256;                 // 1024 uint4 = 128 rows x 8
                int p = idx >> 3, c8 = (idx & 7) * 8;
                *(uint4*)&s_xr[(p + 1) * XSTR + c8] = src[idx];
            }
            if (tid < 16) {   // zero pad rows 0 and 129 (first 64 ch)
                int row = (tid >> 3) ? 129 : 0;
                int c8 = (tid & 7) * 8;
                *(uint4*)&s_xr[row * XSTR + c8] = make_uint4(0, 0, 0, 0);
            }
        } else {
            uint4 z = make_uint4(0, 0, 0, 0);
            for (int i = tid; i < 130 * XSTR / 8; i += 256)
                ((uint4*)s_xr)[i] = z;
        }
        __syncthreads();

#pragma unroll
        for (int kj = 0; kj < 3; kj++) {
            const __half* wt = &s_wo[(ki * 3 + kj) * NOFF * WOSTR];
            int rbase = (p0 + g + kj) * XSTR;
#pragma unroll
            for (int kk = 0; kk < 4; kk++) {
                int j = kk * 16;
                uint32_t a[4], bf[3][2];
                a[0] = *(const uint32_t*)&s_xr[rbase + j + 2 * tg];
                a[1] = *(const uint32_t*)&s_xr[rbase + 8 * XSTR + j + 2 * tg];
                a[2] = *(const uint32_t*)&s_xr[rbase + j + 2 * tg + 8];
                a[3] = *(const uint32_t*)&s_xr[rbase + 8 * XSTR + j + 2 * tg + 8];
#pragma unroll
                for (int nt = 0; nt < 3; nt++) {
                    int n = nt * 8 + g;
                    bf[nt][0] = *(const uint32_t*)&wt[n * WOSTR + j + 2 * tg];
                    bf[nt][1] = *(const uint32_t*)&wt[n * WOSTR + j + 2 * tg + 8];
                }
#pragma unroll
                for (int nt = 0; nt < 3; nt++)
                    MMA_F16(acc[nt], a, bf[nt]);
            }
        }
    }

    __syncthreads();
#pragma unroll
    for (int nt = 0; nt < 3; nt++) {
        int col = nt * 8 + 2 * tg;
        if (col < OOFF) {
            s_off[(p0 + g) * OOFF + col]         = acc[nt][0];
            s_off[(p0 + g) * OOFF + col + 1]     = acc[nt][1];
            s_off[(p0 + g + 8) * OOFF + col]     = acc[nt][2];
            s_off[(p0 + g + 8) * OOFF + col + 1] = acc[nt][3];
        }
    }
    __syncthreads();

    float* op = g_off + (size_t)(b * HWSZ + ho * WW) * OOFF;
    for (int i = tid; i < PIX * OOFF; i += 256)
        op[i] = s_off[i] + boff[i % OOFF];
}

// ---------------- kernel 4: deformable conv, pipelined fp16 MMA ----------------
struct Pref {
    uint4 q00, q01, q10, q11;
    __half2 wA, wB;
    int pp;
};

__device__ __forceinline__ void gather_issue(
    Pref& P, int kidx, int pp, const __half* __restrict__ xb, int cid8,
    const int* s_cA, const int* s_cB, const __half2* s_wA, const __half2* s_wB)
{
    int idx = kidx * PIX + pp;
    int cA = s_cA[idx], cB = s_cB[idx];
    P.wA = s_wA[idx];
    P.wB = s_wB[idx];
    P.pp = pp;
    P.q00 = *(const uint4*)(xb + (cA & 0xFFFF) * CC + cid8);
    P.q01 = *(const uint4*)(xb + (cA >> 16)    * CC + cid8);
    P.q10 = *(const uint4*)(xb + (cB & 0xFFFF) * CC + cid8);
    P.q11 = *(const uint4*)(xb + (cB >> 16)    * CC + cid8);
}

__device__ __forceinline__ void gather_commit(const Pref& P, __half* ss, int cid8) {
    __half2 w00v = __low2half2(P.wA), w01v = __high2half2(P.wA);
    __half2 w10v = __low2half2(P.wB), w11v = __high2half2(P.wB);
    const __half2* h00 = (const __half2*)&P.q00;
    const __half2* h01 = (const __half2*)&P.q01;
    const __half2* h10 = (const __half2*)&P.q10;
    const __half2* h11 = (const __half2*)&P.q11;
    uint4 r;
    __half2* ro = (__half2*)&r;
#pragma unroll
    for (int u = 0; u < 4; u++)
        ro[u] = __hfma2(h11[u], w11v,
                __hfma2(h10[u], w10v,
                __hfma2(h01[u], w01v,
                __hmul2(h00[u], w00v))));
    *(uint4*)&ss[P.pp * SSH + cid8] = r;
}

__device__ __forceinline__ void stage_w(__half* dst, int k, int tid) {
    const uint4* src = (const uint4*)(g_wth + k * CC * OO);
#pragma unroll
    for (int t = 0; t < 2; t++) {
        int idx = tid + t * 256;
        int j = idx >> 3, o8 = (idx & 7) * 8;
        *(uint4*)&dst[j * WSH + o8] = src[idx];
    }
}

__device__ __forceinline__ void mma_half(
    float (&acc)[2][4][4], const __half* ss, const __half* sw,
    int kkbase, int lane, int p0, int n0)
{
#pragma unroll
    for (int kk = kkbase; kk < kkbase + 2; kk++) {
        int j = kk * 16;
        uint32_t A[2][4], Bf[4][2];
#pragma unroll
        for (int mf = 0; mf < 2; mf++) {
            uint32_t addr = smem_u32(
                &ss[(p0 + mf * 16 + (lane & 15)) * SSH + j + ((lane >> 4) << 3)]);
            LDSM_X4(A[mf][0], A[mf][1], A[mf][2], A[mf][3], addr);
        }
#pragma unroll
        for (int q = 0; q < 2; q++) {
            uint32_t addr = smem_u32(
                &sw[(j + (lane & 8) + (lane & 7)) * WSH
                    + n0 + (q * 2 + (lane >> 4)) * 8]);
            LDSM_X4_T(Bf[2 * q][0], Bf[2 * q][1], Bf[2 * q + 1][0], Bf[2 * q + 1][1], addr);
        }
#pragma unroll
        for (int mf = 0; mf < 2; mf++)
#pragma unroll
            for (int nt = 0; nt < 4; nt++)
                MMA_F16(acc[mf][nt], A[mf], Bf[nt]);
    }
}

__global__ __launch_bounds__(256, 2) void k_deform(const float* __restrict__ bias,
                                                   float* __restrict__ out) {
    extern __shared__ __align__(16) char smraw[];
    __half*  s_wb = (__half*)smraw;                      // 2 x [64][WSH]   18432 B
    __half*  s_sb = (__half*)(smraw + 18432);            // 2 x [128][SSH]  36864 B
    int*     s_cA = (int*)(smraw + 55296);               // packed (c00|c01<<16)
    int*     s_cB = s_cA + KK * PIX;                     // packed (c10|c11<<16)
    __half2* s_wA = (__half2*)(s_cB + KK * PIX);         // (w00,w01)
    __half2* s_wB = s_wA + KK * PIX;                     // (w10,w11)
    float*   s_offrow = (float*)(smraw + 18432);         // phase-0 alias of sbuf0
    float*   s_out = (float*)smraw;                      // epilogue alias, 32768 B

    int tid  = threadIdx.x;
    int b    = blockIdx.y;
    int ho   = blockIdx.x;
    int lane = tid & 31;
    int wid  = tid >> 5;

    int g  = lane >> 2;
    int tg = lane & 3;
    int p0 = (wid >> 1) * 32;
    int n0 = (wid & 1) * 32;

    int ppi  = lane >> 3;        // pixel-in-group 0..3 (sampling)
    int cid8 = (lane & 7) * 8;   // channel base (8 ch, 16B)
    int pbase = wid * 4 + ppi;   // this thread's pixel within each 32-group

    const __half* xb = g_xth + (size_t)b * HWSZ * CC;

    // ---- phase 0: offsets row -> smem (coalesced), then all 9 taps' params ----
    {
        const float4* osrc = (const float4*)(g_off + (size_t)(b * HWSZ + ho * WW) * OOFF);
        for (int i = tid; i < PIX * OOFF / 4; i += 256)
            ((float4*)s_offrow)[i] = osrc[i];
    }
    __syncthreads();
    for (int i = tid; i < KK * PIX; i += 256) {
        int p = i & (PIX - 1);
        int k = i >> 7;
        float dy = s_offrow[p * OOFF + 2 * k];
        float dx = s_offrow[p * OOFF + 2 * k + 1];
        int ki = k / 3, kj = k % 3;
        float py = (float)(ho - 1 + ki) + dy;
        float px = (float)(p - 1 + kj) + dx;
        float fy = floorf(py), fx = floorf(px);
        float wy = py - fy, wx = px - fx;
        int iy = (int)fy, ix = (int)fx;
        float vy0 = (iy >= 0 && iy < HH) ? 1.f : 0.f;
        float vy1 = (iy + 1 >= 0 && iy + 1 < HH) ? 1.f : 0.f;
        float vx0 = (ix >= 0 && ix < WW) ? 1.f : 0.f;
        float vx1 = (ix + 1 >= 0 && ix + 1 < WW) ? 1.f : 0.f;
        float w00 = (1.f - wy) * (1.f - wx) * vy0 * vx0;
        float w01 = (1.f - wy) * wx         * vy0 * vx1;
        float w10 = wy         * (1.f - wx) * vy1 * vx0;
        float w11 = wy         * wx         * vy1 * vx1;
        int iy0 = min(max(iy, 0), HH - 1);
        int iy1 = min(max(iy + 1, 0), HH - 1);
        int ix0 = min(max(ix, 0), WW - 1);
        int ix1 = min(max(ix + 1, 0), WW - 1);
        s_cA[i] = (iy0 * WW + ix0) | ((iy0 * WW + ix1) << 16);
        s_cB[i] = (iy1 * WW + ix0) | ((iy1 * WW + ix1) << 16);
        s_wA[i] = __floats2half2_rn(w00, w01);
        s_wB[i] = __floats2half2_rn(w10, w11);
    }
    __syncthreads();   // params visible; s_offrow reads done before sbuf0 overwrite

    float acc[2][4][4];
#pragma unroll
    for (int mf = 0; mf < 2; mf++)
#pragma unroll
        for (int nt = 0; nt < 4; nt++)
#pragma unroll
            for (int c = 0; c < 4; c++) acc[mf][nt][c] = 0.f;

    // ---- prologue: tap 0 into buffer 0 ----
    stage_w(s_wb, 0, tid);
    {
        Pref P;
#pragma unroll
        for (int it = 0; it < 4; it++) {
            gather_issue(P, 0, it * 32 + pbase, xb, cid8, s_cA, s_cB, s_wA, s_wB);
            gather_commit(P, s_sb, cid8);
        }
    }
    __syncthreads();

    // ---- pipelined tap loop: one barrier per tap ----
#pragma unroll 1
    for (int k = 0; k < KK; k++) {
        int cur = k & 1, nxt = cur ^ 1;
        const __half* sw = s_wb + cur * WBUFH;
        const __half* ss = s_sb + cur * SBUFH;
        __half* ssn = s_sb + nxt * SBUFH;
        bool more = (k + 1 < KK);

        Pref P0, P1;
        if (more) {
            gather_issue(P0, k + 1, 0 * 32 + pbase, xb, cid8, s_cA, s_cB, s_wA, s_wB);
            gather_issue(P1, k + 1, 1 * 32 + pbase, xb, cid8, s_cA, s_cB, s_wA, s_wB);
        }
        mma_half(acc, ss, sw, 0, lane, p0, n0);   // LDGs in flight under MMA
        if (more) {
            gather_commit(P0, ssn, cid8);
            gather_commit(P1, ssn, cid8);
            gather_issue(P0, k + 1, 2 * 32 + pbase, xb, cid8, s_cA, s_cB, s_wA, s_wB);
            gather_issue(P1, k + 1, 3 * 32 + pbase, xb, cid8, s_cA, s_cB, s_wA, s_wB);
        }
        mma_half(acc, ss, sw, 2, lane, p0, n0);
        if (more) {
            gather_commit(P0, ssn, cid8);
            gather_commit(P1, ssn, cid8);
            stage_w(s_wb + nxt * WBUFH, k + 1, tid);
        }
        __syncthreads();
    }

    // ---- epilogue: stage output as [o][p] for coalesced NCHW stores ----
#pragma unroll
    for (int mf = 0; mf < 2; mf++)
#pragma unroll
        for (int nt = 0; nt < 4; nt++) {
            int row = p0 + mf * 16 + g;
            int col = n0 + nt * 8 + 2 * tg;
            s_out[col * PIX + row]           = acc[mf][nt][0];
            s_out[(col + 1) * PIX + row]     = acc[mf][nt][1];
            s_out[col * PIX + row + 8]       = acc[mf][nt][2];
            s_out[(col + 1) * PIX + row + 8] = acc[mf][nt][3];
        }
    __syncthreads();

    float* ob = out + (size_t)(b * OO) * HWSZ + ho * WW;
    for (int i = tid; i < OO * PIX / 4; i += 256) {
        int o = i >> 5, p4 = i & 31;
        float4 v = ((const float4*)s_out)[i];
        float bo = bias[o];
        v.x += bo; v.y += bo; v.z += bo; v.w += bo;
        ((float4*)(ob + (size_t)o * HWSZ))[p4] = v;
    }
}

// ---------------- launch ----------------
#define DEFORM_SMEM (18432 + 36864 + 2 * KK * PIX * 4 + 2 * KK * PIX * 4)  // 73728
#define OFFC_SMEM   (31104 + 35360 + 9216)                                 // 75680

extern "C" void kernel_launch(void* const* d_in, const int* in_sizes, int n_in,
                              void* d_out, int out_size) {
    const float* x     = (const float*)d_in[0];
    const float* w_off = (const float*)d_in[1];
    const float* b_off = (const float*)d_in[2];
    const float* w     = (const float*)d_in[3];
    const float* bias  = (const float*)d_in[4];
    float* out = (float*)d_out;

    (void)in_sizes; (void)n_in; (void)out_size;

    cudaFuncSetAttribute(k_offconv, cudaFuncAttributeMaxDynamicSharedMemorySize, OFFC_SMEM);
    cudaFuncSetAttribute(k_deform,  cudaFuncAttributeMaxDynamicSharedMemorySize, DEFORM_SMEM);

    dim3 tpb(32, 8);
    k_transpose<<<dim3(HWSZ / 32, CC / 64, BB), tpb>>>(x);
    k_wprep<<<(KK * CC * OO + 255) / 256, 256>>>(w, w_off);
    k_offconv<<<dim3(HH, BB), 256, OFFC_SMEM>>>(b_off);
    k_deform<<<dim3(HH, BB), 256, DEFORM_SMEM>>>(bias, out);
}